// round 12
// baseline (speedup 1.0000x reference)
#include <cuda_runtime.h>
#include <cuda_fp16.h>
#include <mma.h>
#include <stdint.h>

#define IN_F   256
#define OUT_F  64
#define HALF_F 32
#define MAX_NODES 100000
#define MAX_EDGES 1600000

// ---------------------------------------------------------------------------
// Device-global scratch (allocation-free). Per-chain half-feature buffers.
// ---------------------------------------------------------------------------
__device__ __half g_a0[(size_t)MAX_NODES * HALF_F];  // chain A ping
__device__ __half g_a1[(size_t)MAX_NODES * HALF_F];  // chain A pong
__device__ __half g_b0[(size_t)MAX_NODES * HALF_F];  // chain B ping
__device__ __half g_b1[(size_t)MAX_NODES * HALF_F];  // chain B pong
__device__ int   g_deg[MAX_NODES];
__device__ int   g_off[MAX_NODES];    // partial (per-1024-block) offsets
__device__ int   g_off2[MAX_NODES];   // finalized offsets (scanC output)
__device__ int   g_rank[MAX_EDGES];
__device__ int   g_bsum[128];
__device__ int2  g_csr[MAX_EDGES];    // (src, weight bits), grouped by dst

// ---------------------------------------------------------------------------
// Tensor-core GEMM: x@W.T+b -> fp16, split into chain A ([0:32)) / B ([32:64)).
// ---------------------------------------------------------------------------
#define GM 128
#define ALD 24

union GemmSmem {
    struct {
        __half Ws[OUT_F * IN_F];   // 32768 B
        __half As[GM * ALD];       //  6144 B
    } in;
    float stage[GM * OUT_F];       // 32768 B
};

__global__ __launch_bounds__(256) void sgc_gemm_kernel(
    const float* __restrict__ x, const float* __restrict__ W,
    const float* __restrict__ bias, __half* __restrict__ yA,
    __half* __restrict__ yB, int n_nodes)
{
    using namespace nvcuda;
    __shared__ GemmSmem sm;

    const int t    = threadIdx.x;
    const int warp = t >> 5;
    const int node_base = blockIdx.x * GM;

    {   // Stage W (fp32) -> fp16 smem
        const float4* src = reinterpret_cast<const float4*>(W);
        __half2* dst = reinterpret_cast<__half2*>(sm.in.Ws);
        #pragma unroll
        for (int r = 0; r < 16; r++) {
            int idx4 = t + r * 256;
            float4 v = src[idx4];
            dst[idx4 * 2 + 0] = __floats2half2_rn(v.x, v.y);
            dst[idx4 * 2 + 1] = __floats2half2_rn(v.z, v.w);
        }
    }

    wmma::fragment<wmma::accumulator, 16, 16, 16, float> c[4];
    #pragma unroll
    for (int j = 0; j < 4; j++) wmma::fill_fragment(c[j], 0.0f);

    for (int k0 = 0; k0 < IN_F; k0 += 16) {
        __syncthreads();
        #pragma unroll
        for (int r = 0; r < 2; r++) {
            int idx = t + r * 256;
            int row = idx >> 2;
            int q   = idx & 3;
            int gn  = node_base + row;
            float4 v = make_float4(0.f, 0.f, 0.f, 0.f);
            if (gn < n_nodes)
                v = *reinterpret_cast<const float4*>(x + (size_t)gn * IN_F + k0 + q * 4);
            __half2* p = reinterpret_cast<__half2*>(&sm.in.As[row * ALD + q * 4]);
            p[0] = __floats2half2_rn(v.x, v.y);
            p[1] = __floats2half2_rn(v.z, v.w);
        }
        __syncthreads();

        wmma::fragment<wmma::matrix_a, 16, 16, 16, __half, wmma::row_major> a;
        wmma::load_matrix_sync(a, &sm.in.As[warp * 16 * ALD], ALD);
        #pragma unroll
        for (int j = 0; j < 4; j++) {
            wmma::fragment<wmma::matrix_b, 16, 16, 16, __half, wmma::col_major> bf;
            wmma::load_matrix_sync(bf, &sm.in.Ws[(j * 16) * IN_F + k0], IN_F);
            wmma::mma_sync(c[j], a, bf, c[j]);
        }
    }

    __syncthreads();
    #pragma unroll
    for (int j = 0; j < 4; j++)
        wmma::store_matrix_sync(&sm.stage[(warp * 16) * OUT_F + j * 16], c[j],
                                OUT_F, wmma::mem_row_major);
    __syncthreads();

    {
        int row  = t >> 1;
        int part = t & 1;               // 0 -> chain A, 1 -> chain B
        int gn   = node_base + row;
        if (gn < n_nodes) {
            __half* yb = part ? yB : yA;
            uint4 o[1];
            __half* oh = reinterpret_cast<__half*>(o);
            #pragma unroll
            for (int seg = 0; seg < 4; seg++) {
                #pragma unroll
                for (int cix = 0; cix < 8; cix++) {
                    int f = part * 32 + seg * 8 + cix;
                    oh[cix] = __float2half(sm.stage[row * OUT_F + f] + bias[f]);
                }
                reinterpret_cast<uint4*>(yb + (size_t)gn * HALF_F)[seg] = o[0];
            }
        }
    }
}

// ---------------------------------------------------------------------------
// CSR build
// ---------------------------------------------------------------------------
__global__ void sgc_hist(const int* __restrict__ dst, int* __restrict__ deg,
                         int* __restrict__ rank, int E)
{
    int i = blockIdx.x * blockDim.x + threadIdx.x;
    if (i < E) rank[i] = atomicAdd(&deg[dst[i]], 1);
}

__global__ void sgc_scanA(const int* __restrict__ deg, int* __restrict__ off,
                          int* __restrict__ bsum, int n)
{
    __shared__ int s[256];
    int t = threadIdx.x;
    int base = blockIdx.x * 1024 + t * 4;
    int v0 = (base + 0 < n) ? deg[base + 0] : 0;
    int v1 = (base + 1 < n) ? deg[base + 1] : 0;
    int v2 = (base + 2 < n) ? deg[base + 2] : 0;
    int v3 = (base + 3 < n) ? deg[base + 3] : 0;
    int tsum = v0 + v1 + v2 + v3;
    s[t] = tsum;
    __syncthreads();
    for (int o = 1; o < 256; o <<= 1) {
        int xv = (t >= o) ? s[t - o] : 0;
        __syncthreads();
        s[t] += xv;
        __syncthreads();
    }
    int excl = s[t] - tsum;
    if (t == 255) bsum[blockIdx.x] = s[255];
    if (base + 0 < n) off[base + 0] = excl;
    if (base + 1 < n) off[base + 1] = excl + v0;
    if (base + 2 < n) off[base + 2] = excl + v0 + v1;
    if (base + 3 < n) off[base + 3] = excl + v0 + v1 + v2;
}

// Finalize offsets into SEPARATE off2 (no in-place mutation -> no race with
// the concurrently-running reorder, which reads the partial off).
__global__ void sgc_scanC(const int* __restrict__ off, int* __restrict__ off2,
                          const int* __restrict__ bsum, int n, int nb)
{
    __shared__ int s[128];
    int t = threadIdx.x;
    if (t < 128) s[t] = (t < nb) ? bsum[t] : 0;
    __syncthreads();
    #pragma unroll
    for (int o = 1; o < 128; o <<= 1) {
        int v = (t < 128 && t >= o) ? s[t - o] : 0;
        __syncthreads();
        if (t < 128) s[t] += v;
        __syncthreads();
    }
    int i = blockIdx.x * 256 + t;
    if (i < n) {
        int blk = i >> 10;
        int pref = (blk == 0) ? 0 : s[blk - 1];
        off2[i] = off[i] + pref;
    }
}

// Reorder using PARTIAL off + in-block bsum prefix (reads only immutable data).
__global__ void sgc_reorder(const int* __restrict__ src, const int* __restrict__ dst,
                            const float* __restrict__ wt,
                            const int* __restrict__ offp, const int* __restrict__ rank,
                            const int* __restrict__ bsum, int nb,
                            int2* __restrict__ csr, int E, int T)
{
    __shared__ int s[128];
    int t = threadIdx.x;
    if (t < 128) s[t] = (t < nb) ? bsum[t] : 0;
    __syncthreads();
    #pragma unroll
    for (int o = 1; o < 128; o <<= 1) {
        int v = (t < 128 && t >= o) ? s[t - o] : 0;
        __syncthreads();
        if (t < 128) s[t] += v;
        __syncthreads();
    }

    int i0 = blockIdx.x * blockDim.x + t;
    int i1 = i0 + T, i2 = i0 + 2 * T, i3 = i0 + 3 * T;

    int d0 = (i0 < E) ? dst[i0] : 0;
    int d1 = (i1 < E) ? dst[i1] : 0;
    int d2 = (i2 < E) ? dst[i2] : 0;
    int d3 = (i3 < E) ? dst[i3] : 0;
    int r0 = (i0 < E) ? rank[i0] : 0;
    int r1 = (i1 < E) ? rank[i1] : 0;
    int r2 = (i2 < E) ? rank[i2] : 0;
    int r3 = (i3 < E) ? rank[i3] : 0;
    int o0 = __ldg(offp + d0);
    int o1 = __ldg(offp + d1);
    int o2 = __ldg(offp + d2);
    int o3 = __ldg(offp + d3);
    o0 += (d0 >> 10) ? s[(d0 >> 10) - 1] : 0;
    o1 += (d1 >> 10) ? s[(d1 >> 10) - 1] : 0;
    o2 += (d2 >> 10) ? s[(d2 >> 10) - 1] : 0;
    o3 += (d3 >> 10) ? s[(d3 >> 10) - 1] : 0;
    if (i0 < E) csr[o0 + r0] = make_int2(src[i0], __float_as_int(wt[i0]));
    if (i1 < E) csr[o1 + r1] = make_int2(src[i1], __float_as_int(wt[i1]));
    if (i2 < E) csr[o2 + r2] = make_int2(src[i2], __float_as_int(wt[i2]));
    if (i3 < E) csr[o3 + r3] = make_int2(src[i3], __float_as_int(wt[i3]));
}

// ---------------------------------------------------------------------------
// Half-feature gather hop: 16 lanes/node, half2 (2 feats) per lane.
// Unroll-4, dual accumulators. LAST writes fp32 cols [colOff, colOff+32).
// ---------------------------------------------------------------------------
template <bool LAST>
__global__ __launch_bounds__(512) void sgc_gather_kernel(
    const unsigned* __restrict__ A, __half* __restrict__ Bh,
    float* __restrict__ Bf, int colOff,
    const int* __restrict__ off, const int* __restrict__ deg,
    const int2* __restrict__ csr, int n_nodes)
{
    int warp = threadIdx.x >> 5;
    int lane = threadIdx.x & 31;
    int slot = lane >> 4;
    int fl   = lane & 15;
    int node = blockIdx.x * 32 + warp * 2 + slot;
    if (node >= n_nodes) return;

    int e   = __ldg(off + node);
    int end = e + __ldg(deg + node);

    float2 a0 = {0.f, 0.f}, a1 = {0.f, 0.f};

    for (; e + 4 <= end; e += 4) {
        int2 ew0 = __ldg(&csr[e]);
        int2 ew1 = __ldg(&csr[e + 1]);
        int2 ew2 = __ldg(&csr[e + 2]);
        int2 ew3 = __ldg(&csr[e + 3]);
        unsigned r0 = __ldg(&A[ew0.x * 16 + fl]);
        unsigned r1 = __ldg(&A[ew1.x * 16 + fl]);
        unsigned r2 = __ldg(&A[ew2.x * 16 + fl]);
        unsigned r3 = __ldg(&A[ew3.x * 16 + fl]);
        float2 f0 = __half22float2(*reinterpret_cast<__half2*>(&r0));
        float2 f1 = __half22float2(*reinterpret_cast<__half2*>(&r1));
        float2 f2 = __half22float2(*reinterpret_cast<__half2*>(&r2));
        float2 f3 = __half22float2(*reinterpret_cast<__half2*>(&r3));
        float w0 = __int_as_float(ew0.y), w1 = __int_as_float(ew1.y);
        float w2 = __int_as_float(ew2.y), w3 = __int_as_float(ew3.y);
        a0.x += w0 * f0.x; a0.y += w0 * f0.y;
        a1.x += w1 * f1.x; a1.y += w1 * f1.y;
        a0.x += w2 * f2.x; a0.y += w2 * f2.y;
        a1.x += w3 * f3.x; a1.y += w3 * f3.y;
    }
    for (; e < end; e++) {
        int2 ew = __ldg(&csr[e]);
        unsigned r = __ldg(&A[ew.x * 16 + fl]);
        float2 f = __half22float2(*reinterpret_cast<__half2*>(&r));
        float w = __int_as_float(ew.y);
        a0.x += w * f.x; a0.y += w * f.y;
    }
    a0.x += a1.x; a0.y += a1.y;

    if (LAST) {
        *reinterpret_cast<float2*>(Bf + (size_t)node * OUT_F + colOff + fl * 2) = a0;
    } else {
        __half2 h = __floats2half2_rn(a0.x, a0.y);
        reinterpret_cast<unsigned*>(Bh)[(size_t)node * 16 + fl] =
            *reinterpret_cast<unsigned*>(&h);
    }
}

// ---------------------------------------------------------------------------
// Launch: GEMM + scanC + chain-B hops on side stream; CSR + chain-A on main.
// ---------------------------------------------------------------------------
extern "C" void kernel_launch(void* const* d_in, const int* in_sizes, int n_in,
                              void* d_out, int out_size)
{
    const float* x   = (const float*)d_in[0];
    const float* W   = (const float*)d_in[1];
    const float* b   = (const float*)d_in[2];
    const int*   src = (const int*)  d_in[3];
    const int*   dst = (const int*)  d_in[4];
    const float* wt  = (const float*)d_in[5];

    const int N = in_sizes[0] / IN_F;
    const int E = in_sizes[3];
    float* out  = (float*)d_out;

    __half *a0, *a1, *b0, *b1;
    int *deg, *off, *off2, *rank, *bsum;
    int2 *csr;
    cudaGetSymbolAddress((void**)&a0,   g_a0);
    cudaGetSymbolAddress((void**)&a1,   g_a1);
    cudaGetSymbolAddress((void**)&b0,   g_b0);
    cudaGetSymbolAddress((void**)&b1,   g_b1);
    cudaGetSymbolAddress((void**)&deg,  g_deg);
    cudaGetSymbolAddress((void**)&off,  g_off);
    cudaGetSymbolAddress((void**)&off2, g_off2);
    cudaGetSymbolAddress((void**)&rank, g_rank);
    cudaGetSymbolAddress((void**)&bsum, g_bsum);
    cudaGetSymbolAddress((void**)&csr,  g_csr);

    static cudaStream_t s2 = nullptr;
    static cudaEvent_t evFork = nullptr, evA = nullptr, evC = nullptr,
                       evReo = nullptr, evB = nullptr;
    if (s2 == nullptr) {
        cudaStreamCreateWithFlags(&s2, cudaStreamNonBlocking);
        cudaEventCreateWithFlags(&evFork, cudaEventDisableTiming);
        cudaEventCreateWithFlags(&evA,    cudaEventDisableTiming);
        cudaEventCreateWithFlags(&evC,    cudaEventDisableTiming);
        cudaEventCreateWithFlags(&evReo,  cudaEventDisableTiming);
        cudaEventCreateWithFlags(&evB,    cudaEventDisableTiming);
    }

    const int NB         = (N + 1023) / 1024;
    const int blksN256   = (N + 255) / 256;
    const int blksE256   = (E + 255) / 256;
    const int gemmBlks   = (N + GM - 1) / GM;
    const int gatherBlks = (N + 31) / 32;
    const int reoT       = (E + 3) / 4;
    const int reoBlks    = (reoT + 255) / 256;

    // --- Fork side stream: GEMM (independent of CSR build) ---
    cudaEventRecord(evFork, 0);
    cudaStreamWaitEvent(s2, evFork, 0);
    sgc_gemm_kernel<<<gemmBlks, 256, 0, s2>>>(x, W, b, a0, b0, N);

    // --- Main: CSR build ---
    cudaMemsetAsync(deg, 0, (size_t)N * sizeof(int));
    sgc_hist<<<blksE256, 256>>>(dst, deg, rank, E);
    sgc_scanA<<<NB, 256>>>(deg, off, bsum, N);
    cudaEventRecord(evA, 0);

    // scanC on side stream (writes off2; runs parallel with reorder)
    cudaStreamWaitEvent(s2, evA, 0);
    sgc_scanC<<<blksN256, 256, 0, s2>>>(off, off2, bsum, N, NB);
    cudaEventRecord(evC, s2);

    // reorder on main (reads partial off + bsum only; off never mutated)
    sgc_reorder<<<reoBlks, 256>>>(src, dst, wt, off, rank, bsum, NB, csr, E,
                                  reoBlks * 256);
    cudaEventRecord(evReo, 0);

    // --- Chain A (feats [0:32)) on main: needs scanC(evC); csr main-ordered ---
    cudaStreamWaitEvent(0, evC, 0);
    sgc_gather_kernel<false><<<gatherBlks, 512>>>((const unsigned*)a0, a1,
                                                  nullptr, 0, off2, deg, csr, N);
    sgc_gather_kernel<false><<<gatherBlks, 512>>>((const unsigned*)a1, a0,
                                                  nullptr, 0, off2, deg, csr, N);
    sgc_gather_kernel<true><<<gatherBlks, 512>>>((const unsigned*)a0, nullptr,
                                                 out, 0, off2, deg, csr, N);

    // --- Chain B (feats [32:64)) on s2: needs reorder(evReo); off2 s2-ordered ---
    cudaStreamWaitEvent(s2, evReo, 0);
    sgc_gather_kernel<false><<<gatherBlks, 512, 0, s2>>>((const unsigned*)b0, b1,
                                                  nullptr, 32, off2, deg, csr, N);
    sgc_gather_kernel<false><<<gatherBlks, 512, 0, s2>>>((const unsigned*)b1, b0,
                                                  nullptr, 32, off2, deg, csr, N);
    sgc_gather_kernel<true><<<gatherBlks, 512, 0, s2>>>((const unsigned*)b0, nullptr,
                                                 out, 32, off2, deg, csr, N);
    cudaEventRecord(evB, s2);

    // --- Join ---
    cudaStreamWaitEvent(0, evB, 0);
}

// round 14
// speedup vs baseline: 1.1118x; 1.1118x over previous
#include <cuda_runtime.h>
#include <cuda_fp16.h>
#include <mma.h>
#include <stdint.h>

#define IN_F   256
#define OUT_F  64
#define MAX_NODES 100000
#define MAX_EDGES 1600000

// ---------------------------------------------------------------------------
// Device-global scratch (allocation-free)
// ---------------------------------------------------------------------------
__device__ __half g_h0[(size_t)MAX_NODES * OUT_F];   // fp16 feature ping
__device__ __half g_h1[(size_t)MAX_NODES * OUT_F];   // fp16 feature pong
__device__ int   g_deg[MAX_NODES];
__device__ int   g_off[MAX_NODES];    // partial (per-1024-block) offsets
__device__ int   g_off2[MAX_NODES];   // finalized offsets (scanC output)
__device__ int   g_rank[MAX_EDGES];
__device__ int   g_bsum[128];
__device__ int2  g_csr[MAX_EDGES];    // (src, weight bits), grouped by dst

// ---------------------------------------------------------------------------
// Tensor-core GEMM: y[n,f] = fp16( x@W.T + b ), full-width output.
// ---------------------------------------------------------------------------
#define GM 128
#define ALD 24

union GemmSmem {
    struct {
        __half Ws[OUT_F * IN_F];   // 32768 B
        __half As[GM * ALD];       //  6144 B
    } in;
    float stage[GM * OUT_F];       // 32768 B
};

__global__ __launch_bounds__(256) void sgc_gemm_kernel(
    const float* __restrict__ x, const float* __restrict__ W,
    const float* __restrict__ bias, __half* __restrict__ y, int n_nodes)
{
    using namespace nvcuda;
    __shared__ GemmSmem sm;

    const int t    = threadIdx.x;
    const int warp = t >> 5;
    const int node_base = blockIdx.x * GM;

    {   // Stage W (fp32) -> fp16 smem
        const float4* src = reinterpret_cast<const float4*>(W);
        __half2* dst = reinterpret_cast<__half2*>(sm.in.Ws);
        #pragma unroll
        for (int r = 0; r < 16; r++) {
            int idx4 = t + r * 256;
            float4 v = src[idx4];
            dst[idx4 * 2 + 0] = __floats2half2_rn(v.x, v.y);
            dst[idx4 * 2 + 1] = __floats2half2_rn(v.z, v.w);
        }
    }

    wmma::fragment<wmma::accumulator, 16, 16, 16, float> c[4];
    #pragma unroll
    for (int j = 0; j < 4; j++) wmma::fill_fragment(c[j], 0.0f);

    for (int k0 = 0; k0 < IN_F; k0 += 16) {
        __syncthreads();
        #pragma unroll
        for (int r = 0; r < 2; r++) {
            int idx = t + r * 256;
            int row = idx >> 2;
            int q   = idx & 3;
            int gn  = node_base + row;
            float4 v = make_float4(0.f, 0.f, 0.f, 0.f);
            if (gn < n_nodes)
                v = *reinterpret_cast<const float4*>(x + (size_t)gn * IN_F + k0 + q * 4);
            __half2* p = reinterpret_cast<__half2*>(&sm.in.As[row * ALD + q * 4]);
            p[0] = __floats2half2_rn(v.x, v.y);
            p[1] = __floats2half2_rn(v.z, v.w);
        }
        __syncthreads();

        wmma::fragment<wmma::matrix_a, 16, 16, 16, __half, wmma::row_major> a;
        wmma::load_matrix_sync(a, &sm.in.As[warp * 16 * ALD], ALD);
        #pragma unroll
        for (int j = 0; j < 4; j++) {
            wmma::fragment<wmma::matrix_b, 16, 16, 16, __half, wmma::col_major> bf;
            wmma::load_matrix_sync(bf, &sm.in.Ws[(j * 16) * IN_F + k0], IN_F);
            wmma::mma_sync(c[j], a, bf, c[j]);
        }
    }

    __syncthreads();
    #pragma unroll
    for (int j = 0; j < 4; j++)
        wmma::store_matrix_sync(&sm.stage[(warp * 16) * OUT_F + j * 16], c[j],
                                OUT_F, wmma::mem_row_major);
    __syncthreads();

    {
        int row  = t >> 1;
        int part = (t & 1) * 32;
        int gn   = node_base + row;
        if (gn < n_nodes) {
            uint4 o[1];
            __half* oh = reinterpret_cast<__half*>(o);
            #pragma unroll
            for (int seg = 0; seg < 4; seg++) {
                #pragma unroll
                for (int cix = 0; cix < 8; cix++) {
                    int f = part + seg * 8 + cix;
                    oh[cix] = __float2half(sm.stage[row * OUT_F + f] + bias[f]);
                }
                reinterpret_cast<uint4*>(y + (size_t)gn * OUT_F + part)[seg] = o[0];
            }
        }
    }
}

// ---------------------------------------------------------------------------
// CSR build
// ---------------------------------------------------------------------------
__global__ void sgc_hist(const int* __restrict__ dst, int* __restrict__ deg,
                         int* __restrict__ rank, int E)
{
    int i = blockIdx.x * blockDim.x + threadIdx.x;
    if (i < E) rank[i] = atomicAdd(&deg[dst[i]], 1);
}

__global__ void sgc_scanA(const int* __restrict__ deg, int* __restrict__ off,
                          int* __restrict__ bsum, int n)
{
    __shared__ int s[256];
    int t = threadIdx.x;
    int base = blockIdx.x * 1024 + t * 4;
    int v0 = (base + 0 < n) ? deg[base + 0] : 0;
    int v1 = (base + 1 < n) ? deg[base + 1] : 0;
    int v2 = (base + 2 < n) ? deg[base + 2] : 0;
    int v3 = (base + 3 < n) ? deg[base + 3] : 0;
    int tsum = v0 + v1 + v2 + v3;
    s[t] = tsum;
    __syncthreads();
    for (int o = 1; o < 256; o <<= 1) {
        int xv = (t >= o) ? s[t - o] : 0;
        __syncthreads();
        s[t] += xv;
        __syncthreads();
    }
    int excl = s[t] - tsum;
    if (t == 255) bsum[blockIdx.x] = s[255];
    if (base + 0 < n) off[base + 0] = excl;
    if (base + 1 < n) off[base + 1] = excl + v0;
    if (base + 2 < n) off[base + 2] = excl + v0 + v1;
    if (base + 3 < n) off[base + 3] = excl + v0 + v1 + v2;
}

// Finalize offsets into SEPARATE off2 (no in-place mutation; race-free with
// the concurrently-running reorder, which reads only the partial off).
__global__ void sgc_scanC(const int* __restrict__ off, int* __restrict__ off2,
                          const int* __restrict__ bsum, int n, int nb)
{
    __shared__ int s[128];
    int t = threadIdx.x;
    if (t < 128) s[t] = (t < nb) ? bsum[t] : 0;
    __syncthreads();
    #pragma unroll
    for (int o = 1; o < 128; o <<= 1) {
        int v = (t < 128 && t >= o) ? s[t - o] : 0;
        __syncthreads();
        if (t < 128) s[t] += v;
        __syncthreads();
    }
    int i = blockIdx.x * 256 + t;
    if (i < n) {
        int blk = i >> 10;
        int pref = (blk == 0) ? 0 : s[blk - 1];
        off2[i] = off[i] + pref;
    }
}

// Reorder using PARTIAL off + in-block bsum prefix (reads only immutable data).
__global__ void sgc_reorder(const int* __restrict__ src, const int* __restrict__ dst,
                            const float* __restrict__ wt,
                            const int* __restrict__ offp, const int* __restrict__ rank,
                            const int* __restrict__ bsum, int nb,
                            int2* __restrict__ csr, int E, int T)
{
    __shared__ int s[128];
    int t = threadIdx.x;
    if (t < 128) s[t] = (t < nb) ? bsum[t] : 0;
    __syncthreads();
    #pragma unroll
    for (int o = 1; o < 128; o <<= 1) {
        int v = (t < 128 && t >= o) ? s[t - o] : 0;
        __syncthreads();
        if (t < 128) s[t] += v;
        __syncthreads();
    }

    int i0 = blockIdx.x * blockDim.x + t;
    int i1 = i0 + T, i2 = i0 + 2 * T, i3 = i0 + 3 * T;

    int d0 = (i0 < E) ? dst[i0] : 0;
    int d1 = (i1 < E) ? dst[i1] : 0;
    int d2 = (i2 < E) ? dst[i2] : 0;
    int d3 = (i3 < E) ? dst[i3] : 0;
    int r0 = (i0 < E) ? rank[i0] : 0;
    int r1 = (i1 < E) ? rank[i1] : 0;
    int r2 = (i2 < E) ? rank[i2] : 0;
    int r3 = (i3 < E) ? rank[i3] : 0;
    int o0 = __ldg(offp + d0);
    int o1 = __ldg(offp + d1);
    int o2 = __ldg(offp + d2);
    int o3 = __ldg(offp + d3);
    o0 += (d0 >> 10) ? s[(d0 >> 10) - 1] : 0;
    o1 += (d1 >> 10) ? s[(d1 >> 10) - 1] : 0;
    o2 += (d2 >> 10) ? s[(d2 >> 10) - 1] : 0;
    o3 += (d3 >> 10) ? s[(d3 >> 10) - 1] : 0;
    if (i0 < E) csr[o0 + r0] = make_int2(src[i0], __float_as_int(wt[i0]));
    if (i1 < E) csr[o1 + r1] = make_int2(src[i1], __float_as_int(wt[i1]));
    if (i2 < E) csr[o2 + r2] = make_int2(src[i2], __float_as_int(wt[i2]));
    if (i3 < E) csr[o3 + r3] = make_int2(src[i3], __float_as_int(wt[i3]));
}

// ---------------------------------------------------------------------------
// Gather hop, software-pipelined: 16 lanes/node (2 nodes/warp), uint2 = 4 fp16
// feats per lane (128B/node access). The NEXT group's 4 csr entries are
// prefetched before the current group's feature loads issue, collapsing the
// cross-iteration csr->feature dependency to one exposed L2 latency per group.
// ---------------------------------------------------------------------------
__device__ __forceinline__ void accE(float2& ax, float2& ay, uint2 r, float w)
{
    float2 f0 = __half22float2(*reinterpret_cast<__half2*>(&r.x));
    float2 f1 = __half22float2(*reinterpret_cast<__half2*>(&r.y));
    ax.x += w * f0.x; ax.y += w * f0.y;
    ay.x += w * f1.x; ay.y += w * f1.y;
}

template <bool LAST>
__global__ __launch_bounds__(256) void sgc_gather_kernel(
    const uint2* __restrict__ A, __half* __restrict__ Bh, float* __restrict__ Bf,
    const int* __restrict__ off, const int* __restrict__ deg,
    const int2* __restrict__ csr, int n_nodes)
{
    int warp = threadIdx.x >> 5;
    int lane = threadIdx.x & 31;
    int slot = lane >> 4;
    int fl   = lane & 15;
    int node = blockIdx.x * 16 + warp * 2 + slot;
    if (node >= n_nodes) return;

    int e   = __ldg(off + node);
    int end = e + __ldg(deg + node);

    float2 ax0 = {0.f,0.f}, ay0 = {0.f,0.f};
    float2 ax1 = {0.f,0.f}, ay1 = {0.f,0.f};

    int2 c0, c1, c2, c3;
    bool have = (e + 4 <= end);
    if (have) {
        c0 = __ldg(&csr[e]);
        c1 = __ldg(&csr[e + 1]);
        c2 = __ldg(&csr[e + 2]);
        c3 = __ldg(&csr[e + 3]);
    }

    for (; e + 8 <= end; e += 4) {
        // Prefetch next group's csr entries (independent of current features)
        int2 n0 = __ldg(&csr[e + 4]);
        int2 n1 = __ldg(&csr[e + 5]);
        int2 n2 = __ldg(&csr[e + 6]);
        int2 n3 = __ldg(&csr[e + 7]);
        // Current group's feature loads (addresses ready since last iter)
        uint2 r0 = __ldg(&A[c0.x * 16 + fl]);
        uint2 r1 = __ldg(&A[c1.x * 16 + fl]);
        uint2 r2 = __ldg(&A[c2.x * 16 + fl]);
        uint2 r3 = __ldg(&A[c3.x * 16 + fl]);
        accE(ax0, ay0, r0, __int_as_float(c0.y));
        accE(ax1, ay1, r1, __int_as_float(c1.y));
        accE(ax0, ay0, r2, __int_as_float(c2.y));
        accE(ax1, ay1, r3, __int_as_float(c3.y));
        c0 = n0; c1 = n1; c2 = n2; c3 = n3;
    }
    if (have) {   // drain the last full group already resident in c0..c3
        uint2 r0 = __ldg(&A[c0.x * 16 + fl]);
        uint2 r1 = __ldg(&A[c1.x * 16 + fl]);
        uint2 r2 = __ldg(&A[c2.x * 16 + fl]);
        uint2 r3 = __ldg(&A[c3.x * 16 + fl]);
        accE(ax0, ay0, r0, __int_as_float(c0.y));
        accE(ax1, ay1, r1, __int_as_float(c1.y));
        accE(ax0, ay0, r2, __int_as_float(c2.y));
        accE(ax1, ay1, r3, __int_as_float(c3.y));
        e += 4;
    }
    for (; e < end; e++) {
        int2 ew = __ldg(&csr[e]);
        uint2 r = __ldg(&A[ew.x * 16 + fl]);
        accE(ax0, ay0, r, __int_as_float(ew.y));
    }
    ax0.x += ax1.x; ax0.y += ax1.y;
    ay0.x += ay1.x; ay0.y += ay1.y;

    if (LAST) {
        reinterpret_cast<float4*>(Bf)[(size_t)node * 16 + fl] =
            make_float4(ax0.x, ax0.y, ay0.x, ay0.y);
    } else {
        __half2 h0 = __floats2half2_rn(ax0.x, ax0.y);
        __half2 h1 = __floats2half2_rn(ay0.x, ay0.y);
        uint2 o;
        o.x = *reinterpret_cast<unsigned*>(&h0);
        o.y = *reinterpret_cast<unsigned*>(&h1);
        reinterpret_cast<uint2*>(Bh)[(size_t)node * 16 + fl] = o;
    }
}

// ---------------------------------------------------------------------------
// Launch: GEMM + scanC on side stream; CSR build + hops on main. Race-free.
// ---------------------------------------------------------------------------
extern "C" void kernel_launch(void* const* d_in, const int* in_sizes, int n_in,
                              void* d_out, int out_size)
{
    const float* x   = (const float*)d_in[0];
    const float* W   = (const float*)d_in[1];
    const float* b   = (const float*)d_in[2];
    const int*   src = (const int*)  d_in[3];
    const int*   dst = (const int*)  d_in[4];
    const float* wt  = (const float*)d_in[5];

    const int N = in_sizes[0] / IN_F;
    const int E = in_sizes[3];
    float* out  = (float*)d_out;

    __half *h0, *h1;
    int *deg, *off, *off2, *rank, *bsum;
    int2 *csr;
    cudaGetSymbolAddress((void**)&h0,   g_h0);
    cudaGetSymbolAddress((void**)&h1,   g_h1);
    cudaGetSymbolAddress((void**)&deg,  g_deg);
    cudaGetSymbolAddress((void**)&off,  g_off);
    cudaGetSymbolAddress((void**)&off2, g_off2);
    cudaGetSymbolAddress((void**)&rank, g_rank);
    cudaGetSymbolAddress((void**)&bsum, g_bsum);
    cudaGetSymbolAddress((void**)&csr,  g_csr);

    static cudaStream_t s2 = nullptr;
    static cudaEvent_t evFork = nullptr, evA = nullptr, evC = nullptr;
    if (s2 == nullptr) {
        cudaStreamCreateWithFlags(&s2, cudaStreamNonBlocking);
        cudaEventCreateWithFlags(&evFork, cudaEventDisableTiming);
        cudaEventCreateWithFlags(&evA,    cudaEventDisableTiming);
        cudaEventCreateWithFlags(&evC,    cudaEventDisableTiming);
    }

    const int NB         = (N + 1023) / 1024;
    const int blksN256   = (N + 255) / 256;
    const int blksE256   = (E + 255) / 256;
    const int gemmBlks   = (N + GM - 1) / GM;
    const int gatherBlks = (N + 15) / 16;
    const int reoT       = (E + 3) / 4;
    const int reoBlks    = (reoT + 255) / 256;

    // --- Fork side stream: GEMM (independent of CSR build) ---
    cudaEventRecord(evFork, 0);
    cudaStreamWaitEvent(s2, evFork, 0);
    sgc_gemm_kernel<<<gemmBlks, 256, 0, s2>>>(x, W, b, h0, N);

    // --- Main: CSR build ---
    cudaMemsetAsync(deg, 0, (size_t)N * sizeof(int));
    sgc_hist<<<blksE256, 256>>>(dst, deg, rank, E);
    sgc_scanA<<<NB, 256>>>(deg, off, bsum, N);
    cudaEventRecord(evA, 0);

    // scanC on side stream (writes off2; runs parallel with reorder on main)
    cudaStreamWaitEvent(s2, evA, 0);
    sgc_scanC<<<blksN256, 256, 0, s2>>>(off, off2, bsum, N, NB);
    cudaEventRecord(evC, s2);

    // reorder on main (reads partial off + bsum only; off never mutated)
    sgc_reorder<<<reoBlks, 256>>>(src, dst, wt, off, rank, bsum, NB, csr, E,
                                  reoBlks * 256);

    // --- Join (gemm + scanC), then 3 full-width gather hops on main ---
    cudaStreamWaitEvent(0, evC, 0);
    sgc_gather_kernel<false><<<gatherBlks, 256>>>((const uint2*)h0, h1, nullptr,
                                                  off2, deg, csr, N);
    sgc_gather_kernel<false><<<gatherBlks, 256>>>((const uint2*)h1, h0, nullptr,
                                                  off2, deg, csr, N);
    sgc_gather_kernel<true><<<gatherBlks, 256>>>((const uint2*)h0, nullptr, out,
                                                 off2, deg, csr, N);
}